// round 3
// baseline (speedup 1.0000x reference)
#include <cuda_runtime.h>
#include <math.h>

// ---------------- problem constants ----------------
#define T_STEPS 512
#define B_SZ    64
#define D_SZ    512
#define H_SZ    1024
#define G4      4096          // 4*H
#define BH      (B_SZ*H_SZ)   // 65536

// ---------------- scratch / barrier state ----------------
__device__ float g_xg[(size_t)T_STEPS * B_SZ * G4];   // 512 MB, Xg = X@Wx + b
__device__ unsigned g_arrive = 0;
__device__ unsigned g_sense  = 0;

// ---------------- packed f32x2 helpers (Blackwell) ----------------
union F2 { unsigned long long u; float2 f; };

__device__ __forceinline__ void ffma2(F2& d, const F2 a, const F2 b) {
    asm("fma.rn.f32x2 %0, %1, %2, %0;" : "+l"(d.u) : "l"(a.u), "l"(b.u));
}
__device__ __forceinline__ F2 pack2(float lo, float hi) {
    F2 r; asm("mov.b64 %0, {%1, %2};" : "=l"(r.u) : "f"(lo), "f"(hi)); return r;
}

// ====================================================================
// Kernel 1: Xg[m, gate*1024 + n] = X[m,:] @ Wx_gate[:, n] + b_gate[n]
// M = 32768 (t*64+b), K = 512, N = 1024 per gate.
// 128x128 tile, Ktile=16, 256 threads, 8x8 per-thread microtile via FFMA2.
// ====================================================================
__global__ void __launch_bounds__(256, 2) xg_gemm(
    const float* __restrict__ X,
    const float* __restrict__ Wx0, const float* __restrict__ Wx1,
    const float* __restrict__ Wx2, const float* __restrict__ Wx3,
    const float* __restrict__ b0p, const float* __restrict__ b1p,
    const float* __restrict__ b2p, const float* __restrict__ b3p)
{
    __shared__ float sA[16 * 132];   // [k][row], padded stride 132
    __shared__ float sB[16 * 128];   // [k][n]

    const int tid   = threadIdx.x;
    const int m0    = blockIdx.y * 128;
    const int ntile = blockIdx.x;          // 0..31
    const int gate  = ntile >> 3;
    const int nb    = (ntile & 7) * 128;   // column base within gate

    const float* Wg = (gate == 0) ? Wx0 : (gate == 1) ? Wx1 : (gate == 2) ? Wx2 : Wx3;
    const float* bg = (gate == 0) ? b0p : (gate == 1) ? b1p : (gate == 2) ? b2p : b3p;

    const int ty = tid >> 4;   // 0..15 -> rows ty*8..+7
    const int tx = tid & 15;   // 0..15 -> cols tx*8..+7

    F2 acc[8][4];
    #pragma unroll
    for (int i = 0; i < 8; ++i)
        #pragma unroll
        for (int j = 0; j < 4; ++j) { acc[i][j].f.x = 0.f; acc[i][j].f.y = 0.f; }

    for (int k0 = 0; k0 < D_SZ; k0 += 16) {
        __syncthreads();
        #pragma unroll
        for (int r = 0; r < 2; ++r) {
            int idx = tid + r * 256;               // 0..511
            {   // A: 128 rows x 16 k, float4 along k
                int row = idx >> 2, kq = (idx & 3) * 4;
                float4 v = *(const float4*)&X[(size_t)(m0 + row) * D_SZ + k0 + kq];
                sA[(kq + 0) * 132 + row] = v.x;
                sA[(kq + 1) * 132 + row] = v.y;
                sA[(kq + 2) * 132 + row] = v.z;
                sA[(kq + 3) * 132 + row] = v.w;
            }
            {   // B: 16 k x 128 n, float4 along n
                int kk = idx >> 5, nq = (idx & 31) * 4;
                *(float4*)&sB[kk * 128 + nq] =
                    *(const float4*)&Wg[(size_t)(k0 + kk) * H_SZ + nb + nq];
            }
        }
        __syncthreads();

        #pragma unroll
        for (int kk = 0; kk < 16; ++kk) {
            float4 a0 = *(const float4*)&sA[kk * 132 + ty * 8];
            float4 a1 = *(const float4*)&sA[kk * 132 + ty * 8 + 4];
            float4 q0 = *(const float4*)&sB[kk * 128 + tx * 8];
            float4 q1 = *(const float4*)&sB[kk * 128 + tx * 8 + 4];
            F2 bb[4];
            bb[0].f = make_float2(q0.x, q0.y); bb[1].f = make_float2(q0.z, q0.w);
            bb[2].f = make_float2(q1.x, q1.y); bb[3].f = make_float2(q1.z, q1.w);
            float av[8] = {a0.x, a0.y, a0.z, a0.w, a1.x, a1.y, a1.z, a1.w};
            #pragma unroll
            for (int i = 0; i < 8; ++i) {
                F2 ai = pack2(av[i], av[i]);
                #pragma unroll
                for (int j = 0; j < 4; ++j) ffma2(acc[i][j], ai, bb[j]);
            }
        }
    }

    // epilogue: add bias, store
    float4 bv0 = *(const float4*)&bg[nb + tx * 8];
    float4 bv1 = *(const float4*)&bg[nb + tx * 8 + 4];
    #pragma unroll
    for (int i = 0; i < 8; ++i) {
        size_t row = (size_t)(m0 + ty * 8 + i);
        float* op = g_xg + row * G4 + (size_t)gate * H_SZ + nb + tx * 8;
        float4 o0, o1;
        o0.x = acc[i][0].f.x + bv0.x; o0.y = acc[i][0].f.y + bv0.y;
        o0.z = acc[i][1].f.x + bv0.z; o0.w = acc[i][1].f.y + bv0.w;
        o1.x = acc[i][2].f.x + bv1.x; o1.y = acc[i][2].f.y + bv1.y;
        o1.z = acc[i][3].f.x + bv1.z; o1.w = acc[i][3].f.y + bv1.w;
        *(float4*)op       = o0;
        *(float4*)(op + 4) = o1;
    }
}

// ====================================================================
// Kernel 2: persistent recurrence.
// 128 CTAs x 256 threads, 1 CTA/SM (all co-resident -> grid barrier OK).
// CTA j owns h in [j*8, j*8+8): SMEM-resident Wh slice [1024, 4gates*8] (128KB).
// Per step: G[64,32] = Xg_slice + Hprev @ Wh_slice, then gates -> C,H.
// H_t lives directly in `out` (outputs ARE H). C lives in registers.
// Barrier count per launch = 512 (even) -> g_sense/g_arrive self-restore,
// so the kernel is deterministic across graph replays.
// ====================================================================
#define NCTA 128
#define SH_STRIDE 130                    // 64 x (128+2) pad: conflict-free
#define SW_FLOATS (1024 * 32)            // 131072 B
#define SH_OFF    SW_FLOATS
#define SG_OFF    (SW_FLOATS + 64 * SH_STRIDE)
#define SMEM_FLOATS (SG_OFF + 64 * 32)
#define SMEM_BYTES (SMEM_FLOATS * 4)     // 172544 B

__device__ __forceinline__ void grid_barrier(unsigned& sense) {
    __threadfence();          // release this thread's H writes (gpu scope)
    __syncthreads();
    if (threadIdx.x == 0) {
        unsigned s = sense ^ 1u;
        unsigned old = atomicAdd(&g_arrive, 1u);
        if (old == NCTA - 1) {
            atomicExch(&g_arrive, 0u);
            __threadfence();
            atomicExch(&g_sense, s);
        } else {
            while (*(volatile unsigned*)&g_sense != s) { __nanosleep(32); }
        }
        __threadfence();      // acquire
        sense = s;
    }
    __syncthreads();
}

__global__ void __launch_bounds__(256, 1) lstm_rec(
    const float* __restrict__ Wh0, const float* __restrict__ Wh1,
    const float* __restrict__ Wh2, const float* __restrict__ Wh3,
    float* __restrict__ out, int out_size)
{
    extern __shared__ float sm[];
    float* sW = sm;                 // [k][32]  : 4 gates x 8 h cols
    float* sH = sm + SH_OFF;        // [b][128+pad] chunk of Hprev
    float* sG = sm + SG_OFF;        // [b][gate][8]

    const int tid = threadIdx.x;
    const int h0  = blockIdx.x * 8;

    // load Wh slice once (each element read exactly once chip-wide)
    for (int i = tid; i < SW_FLOATS; i += 256) {
        int k = i >> 5; int c = i & 31; int gate = c >> 3; int hh = c & 7;
        const float* w = (gate == 0) ? Wh0 : (gate == 1) ? Wh1 : (gate == 2) ? Wh2 : Wh3;
        sW[i] = w[(size_t)k * H_SZ + h0 + hh];
    }

    const int b  = tid >> 2;        // 0..63
    const int cg = tid & 3;         // gate 0..3, cols cg*8..+7 of slice
    const float4* sW4 = (const float4*)sW;
    const int wcol = cg * 2;

    // elementwise ownership: thread handles (bb0, hh0) and (bb0, hh0+1)
    const int p0 = tid * 2, bb0 = p0 >> 3, hh0 = p0 & 7;
    float c_reg0 = 0.f, c_reg1 = 0.f;
    unsigned sense = 0;

    __syncthreads();   // sW ready

    for (int t = 0; t < T_STEPS; ++t) {
        F2 acc[4];
        #pragma unroll
        for (int j = 0; j < 4; ++j) { acc[j].f.x = 0.f; acc[j].f.y = 0.f; }

        if (t > 0) {
            const float* Hprev = out + (size_t)(t - 1) * BH;
            for (int kc = 0; kc < 8; ++kc) {
                const int k0 = kc * 128;
                __syncthreads();
                #pragma unroll
                for (int r = 0; r < 32; ++r) {       // 64x128 chunk, coalesced
                    int i = tid + r * 256;
                    int lb = i >> 7, kk = i & 127;
                    sH[lb * SH_STRIDE + kk] = Hprev[(size_t)lb * H_SZ + k0 + kk];
                }
                __syncthreads();
                const float* hrow = sH + b * SH_STRIDE;
                #pragma unroll 4
                for (int kk = 0; kk < 128; ++kk) {
                    float h = hrow[kk];
                    F2 h2 = pack2(h, h);
                    const int k = k0 + kk;
                    float4 w0 = sW4[k * 8 + wcol];
                    float4 w1 = sW4[k * 8 + wcol + 1];
                    F2 wa, wb, wc, wd;
                    wa.f = make_float2(w0.x, w0.y); wb.f = make_float2(w0.z, w0.w);
                    wc.f = make_float2(w1.x, w1.y); wd.f = make_float2(w1.z, w1.w);
                    ffma2(acc[0], h2, wa);
                    ffma2(acc[1], h2, wb);
                    ffma2(acc[2], h2, wc);
                    ffma2(acc[3], h2, wd);
                }
            }
        }

        // add xg (bias already folded in)
        {
            const float* xp = g_xg + ((size_t)t * B_SZ + b) * G4 + (size_t)cg * H_SZ + h0;
            float4 x0 = *(const float4*)xp;
            float4 x1 = *(const float4*)(xp + 4);
            acc[0].f.x += x0.x; acc[0].f.y += x0.y;
            acc[1].f.x += x0.z; acc[1].f.y += x0.w;
            acc[2].f.x += x1.x; acc[2].f.y += x1.y;
            acc[3].f.x += x1.z; acc[3].f.y += x1.w;
        }

        __syncthreads();   // sG free to overwrite
        {
            float* gp = sG + b * 32 + cg * 8;
            gp[0] = acc[0].f.x; gp[1] = acc[0].f.y;
            gp[2] = acc[1].f.x; gp[3] = acc[1].f.y;
            gp[4] = acc[2].f.x; gp[5] = acc[2].f.y;
            gp[6] = acc[3].f.x; gp[7] = acc[3].f.y;
        }
        __syncthreads();

        // elementwise gates: 2 consecutive h per thread
        float Hn0, Hn1, Cn0, Cn1;
        {
            const float* gb = sG + bb0 * 32;
            float gi = gb[hh0],      gf = gb[8 + hh0];
            float go = gb[16 + hh0], gc = gb[24 + hh0];
            float I = 1.f / (1.f + expf(-gi));
            float F = 1.f / (1.f + expf(-gf));
            float O = 1.f / (1.f + expf(-go));
            Cn0 = F * c_reg0 + I * tanhf(gc);
            c_reg0 = Cn0;
            Hn0 = O * tanhf(Cn0);

            gi = gb[hh0 + 1];      gf = gb[8 + hh0 + 1];
            go = gb[16 + hh0 + 1]; gc = gb[24 + hh0 + 1];
            I = 1.f / (1.f + expf(-gi));
            F = 1.f / (1.f + expf(-gf));
            O = 1.f / (1.f + expf(-go));
            Cn1 = F * c_reg1 + I * tanhf(gc);
            c_reg1 = Cn1;
            Hn1 = O * tanhf(Cn1);
        }

        {
            size_t idx = (size_t)bb0 * H_SZ + h0 + hh0;
            float2 hv = make_float2(Hn0, Hn1);
            *(float2*)&out[(size_t)t * BH + idx] = hv;
            if (t == T_STEPS - 1) {
                size_t base = (size_t)T_STEPS * BH;
                if ((size_t)out_size >= base + (size_t)BH)
                    *(float2*)&out[base + idx] = hv;                      // Hf
                if ((size_t)out_size >= base + 2 * (size_t)BH)
                    *(float2*)&out[base + BH + idx] = make_float2(Cn0, Cn1); // Cf
            }
        }

        grid_barrier(sense);   // 512 barriers total (even -> state restored)
    }
}

// ====================================================================
// launch
// ====================================================================
extern "C" void kernel_launch(void* const* d_in, const int* in_sizes, int n_in,
                              void* d_out, int out_size) {
    const float* X   = (const float*)d_in[0];
    const float* Wxi = (const float*)d_in[1];
    const float* Whi = (const float*)d_in[2];
    const float* bi  = (const float*)d_in[3];
    const float* Wxf = (const float*)d_in[4];
    const float* Whf = (const float*)d_in[5];
    const float* bf  = (const float*)d_in[6];
    const float* Wxo = (const float*)d_in[7];
    const float* Who = (const float*)d_in[8];
    const float* bo  = (const float*)d_in[9];
    const float* Wxc = (const float*)d_in[10];
    const float* Whc = (const float*)d_in[11];
    const float* bc  = (const float*)d_in[12];
    float* out = (float*)d_out;

    // Phase 1: input projections for all T as one big GEMM
    dim3 gA(32, 256, 1);
    xg_gemm<<<gA, 256>>>(X, Wxi, Wxf, Wxo, Wxc, bi, bf, bo, bc);

    // Phase 2: persistent recurrence (needs >48KB dynamic SMEM)
    cudaFuncSetAttribute(lstm_rec, cudaFuncAttributeMaxDynamicSharedMemorySize,
                         SMEM_BYTES);
    lstm_rec<<<NCTA, 256, SMEM_BYTES>>>(Whi, Whf, Who, Whc, out, out_size);
}

// round 6
// speedup vs baseline: 2.7745x; 2.7745x over previous
#include <cuda_runtime.h>
#include <cuda_bf16.h>
#include <cstdint>
#include <math.h>

// ---------------- problem constants ----------------
#define T_STEPS 512
#define B_SZ    64
#define D_SZ    512
#define H_SZ    1024
#define G4      4096          // 4*H
#define BH      (B_SZ*H_SZ)   // 65536
#define NCTA    128

// ---------------- global scratch / barrier state ----------------
__device__ float g_xg[(size_t)T_STEPS * B_SZ * G4];   // 512 MB, Xg = X@Wx + b
__device__ __nv_bfloat16 g_Hh[2][BH];                 // H split-bf16 hi, ping-pong
__device__ __nv_bfloat16 g_Hl[2][BH];                 // H split-bf16 lo
__device__ unsigned g_arrive = 0;
__device__ unsigned g_sense  = 0;

// ---------------- packed f32x2 helpers (Blackwell) ----------------
union F2 { unsigned long long u; float2 f; };
__device__ __forceinline__ void ffma2(F2& d, const F2 a, const F2 b) {
    asm("fma.rn.f32x2 %0, %1, %2, %0;" : "+l"(d.u) : "l"(a.u), "l"(b.u));
}
__device__ __forceinline__ F2 pack2(float lo, float hi) {
    F2 r; asm("mov.b64 %0, {%1, %2};" : "=l"(r.u) : "f"(lo), "f"(hi)); return r;
}

// ---------------- helpers ----------------
__device__ __forceinline__ uint32_t smem_u32(const void* p) {
    uint32_t a;
    asm("{ .reg .u64 t; cvta.to.shared.u64 t, %1; cvt.u32.u64 %0, t; }" : "=r"(a) : "l"(p));
    return a;
}
// ldmatrix: 4x 8x8 b16 matrices (A operand, row-major smem)
__device__ __forceinline__ void ldsm_x4(uint32_t* r, uint32_t addr) {
    asm volatile("ldmatrix.sync.aligned.m8n8.x4.shared.b16 {%0,%1,%2,%3}, [%4];"
                 : "=r"(r[0]), "=r"(r[1]), "=r"(r[2]), "=r"(r[3]) : "r"(addr));
}
// ldmatrix transposed (B operand: smem row-major [k][n] -> .col fragment)
__device__ __forceinline__ void ldsm_x4t(uint32_t* r, uint32_t addr) {
    asm volatile("ldmatrix.sync.aligned.m8n8.x4.trans.shared.b16 {%0,%1,%2,%3}, [%4];"
                 : "=r"(r[0]), "=r"(r[1]), "=r"(r[2]), "=r"(r[3]) : "r"(addr));
}
// mma m16n8k16 bf16 (sm_80+, compiles at compute_100)
__device__ __forceinline__ void mma16816(float* c, const uint32_t* a, uint32_t b0, uint32_t b1) {
    asm volatile(
        "mma.sync.aligned.m16n8k16.row.col.f32.bf16.bf16.f32 "
        "{%0,%1,%2,%3}, {%4,%5,%6,%7}, {%8,%9}, {%0,%1,%2,%3};"
        : "+f"(c[0]), "+f"(c[1]), "+f"(c[2]), "+f"(c[3])
        : "r"(a[0]), "r"(a[1]), "r"(a[2]), "r"(a[3]), "r"(b0), "r"(b1));
}

// ====================================================================
// Kernel 1: Xg[m, gate*1024 + n] = X[m,:] @ Wx_gate[:, n] + b_gate[n]
// (unchanged from passing R3 version; fp32 SIMT FFMA2)
// ====================================================================
__global__ void __launch_bounds__(256, 2) xg_gemm(
    const float* __restrict__ X,
    const float* __restrict__ Wx0, const float* __restrict__ Wx1,
    const float* __restrict__ Wx2, const float* __restrict__ Wx3,
    const float* __restrict__ b0p, const float* __restrict__ b1p,
    const float* __restrict__ b2p, const float* __restrict__ b3p)
{
    __shared__ float sA[16 * 132];
    __shared__ float sB[16 * 128];

    const int tid   = threadIdx.x;
    const int m0    = blockIdx.y * 128;
    const int ntile = blockIdx.x;
    const int gate  = ntile >> 3;
    const int nb    = (ntile & 7) * 128;

    const float* Wg = (gate == 0) ? Wx0 : (gate == 1) ? Wx1 : (gate == 2) ? Wx2 : Wx3;
    const float* bg = (gate == 0) ? b0p : (gate == 1) ? b1p : (gate == 2) ? b2p : b3p;

    const int ty = tid >> 4;
    const int tx = tid & 15;

    F2 acc[8][4];
    #pragma unroll
    for (int i = 0; i < 8; ++i)
        #pragma unroll
        for (int j = 0; j < 4; ++j) { acc[i][j].f.x = 0.f; acc[i][j].f.y = 0.f; }

    for (int k0 = 0; k0 < D_SZ; k0 += 16) {
        __syncthreads();
        #pragma unroll
        for (int r = 0; r < 2; ++r) {
            int idx = tid + r * 256;
            {
                int row = idx >> 2, kq = (idx & 3) * 4;
                float4 v = *(const float4*)&X[(size_t)(m0 + row) * D_SZ + k0 + kq];
                sA[(kq + 0) * 132 + row] = v.x;
                sA[(kq + 1) * 132 + row] = v.y;
                sA[(kq + 2) * 132 + row] = v.z;
                sA[(kq + 3) * 132 + row] = v.w;
            }
            {
                int kk = idx >> 5, nq = (idx & 31) * 4;
                *(float4*)&sB[kk * 128 + nq] =
                    *(const float4*)&Wg[(size_t)(k0 + kk) * H_SZ + nb + nq];
            }
        }
        __syncthreads();

        #pragma unroll
        for (int kk = 0; kk < 16; ++kk) {
            float4 a0 = *(const float4*)&sA[kk * 132 + ty * 8];
            float4 a1 = *(const float4*)&sA[kk * 132 + ty * 8 + 4];
            float4 q0 = *(const float4*)&sB[kk * 128 + tx * 8];
            float4 q1 = *(const float4*)&sB[kk * 128 + tx * 8 + 4];
            F2 bb[4];
            bb[0].f = make_float2(q0.x, q0.y); bb[1].f = make_float2(q0.z, q0.w);
            bb[2].f = make_float2(q1.x, q1.y); bb[3].f = make_float2(q1.z, q1.w);
            float av[8] = {a0.x, a0.y, a0.z, a0.w, a1.x, a1.y, a1.z, a1.w};
            #pragma unroll
            for (int i = 0; i < 8; ++i) {
                F2 ai = pack2(av[i], av[i]);
                #pragma unroll
                for (int j = 0; j < 4; ++j) ffma2(acc[i][j], ai, bb[j]);
            }
        }
    }

    float4 bv0 = *(const float4*)&bg[nb + tx * 8];
    float4 bv1 = *(const float4*)&bg[nb + tx * 8 + 4];
    #pragma unroll
    for (int i = 0; i < 8; ++i) {
        size_t row = (size_t)(m0 + ty * 8 + i);
        float* op = g_xg + row * G4 + (size_t)gate * H_SZ + nb + tx * 8;
        float4 o0, o1;
        o0.x = acc[i][0].f.x + bv0.x; o0.y = acc[i][0].f.y + bv0.y;
        o0.z = acc[i][1].f.x + bv0.z; o0.w = acc[i][1].f.y + bv0.w;
        o1.x = acc[i][2].f.x + bv1.x; o1.y = acc[i][2].f.y + bv1.y;
        o1.z = acc[i][3].f.x + bv1.z; o1.w = acc[i][3].f.y + bv1.w;
        *(float4*)op       = o0;
        *(float4*)(op + 4) = o1;
    }
}

// ====================================================================
// Kernel 2: persistent mma.sync recurrence.
// 128 CTAs x 256 threads, 1/SM. CTA j owns h-slice [j*8,j*8+8) for 4 gates
// -> 32 gate columns. Wh slice resident in SMEM as split-bf16 [k][32]
// (stride 40, conflict-free ldmatrix). Per step:
//   G[64,32] = Hs@Whslice via 3-pass split-bf16 m16n8k16 mma.sync.
//   8 warps = 4 m-tiles x 2 n-pairs, full K per warp (no reduction).
//   H streamed in 16 K=64 chunks, register-prefetch double buffer.
// Epilogue: fragments -> sG -> warps 0-1 gate math -> out + split-bf16 H.
// ====================================================================

// SMEM byte offsets
#define RM_W_HI 0                      // 1024 x 40 bf16 = 81920
#define RM_W_LO 81920                  // 81920
#define RM_A    163840                 // 2 bufs x {hi,lo} x 64x72 bf16 = 4x9216
#define RM_XG   200704                 // 64x32 f32 = 8192
#define RM_G    208896                 // 64x33 f32 = 8448
#define RM_TOTAL 217344

__device__ __forceinline__ void grid_barrier(unsigned& sense) {
    __threadfence();
    __syncthreads();
    if (threadIdx.x == 0) {
        unsigned s = sense ^ 1u;
        unsigned old = atomicAdd(&g_arrive, 1u);
        if (old == NCTA - 1) {
            atomicExch(&g_arrive, 0u);
            __threadfence();
            atomicExch(&g_sense, s);
        } else {
            while (*(volatile unsigned*)&g_sense != s) { __nanosleep(32); }
        }
        __threadfence();
        sense = s;
    }
    __syncthreads();
}

__global__ void __launch_bounds__(256, 1) lstm_rec(
    const float* __restrict__ Wh0, const float* __restrict__ Wh1,
    const float* __restrict__ Wh2, const float* __restrict__ Wh3,
    float* __restrict__ out, int out_size)
{
    extern __shared__ char smc[];
    const uint32_t smem_base = smem_u32(smc);
    const int tid  = threadIdx.x;
    const int wid  = tid >> 5;
    const int lane = tid & 31;
    const int h0   = blockIdx.x * 8;

    // ---- fill resident Wh slice: [k][n=gate*8+hh], stride 40, hi+lo ----
    {
        __nv_bfloat16* wh = (__nv_bfloat16*)(smc + RM_W_HI);
        __nv_bfloat16* wl = (__nv_bfloat16*)(smc + RM_W_LO);
        for (int i = tid; i < 32 * 1024; i += 256) {
            int k = i >> 5, n = i & 31;
            int gate = n >> 3;
            const float* W = (gate == 0) ? Wh0 : (gate == 1) ? Wh1
                             : (gate == 2) ? Wh2 : Wh3;
            float w = W[(size_t)k * H_SZ + h0 + (n & 7)];
            __nv_bfloat16 hi = __float2bfloat16(w);
            __nv_bfloat16 lo = __float2bfloat16(w - __bfloat162float(hi));
            wh[k * 40 + n] = hi;
            wl[k * 40 + n] = lo;
        }
    }
    __syncthreads();

    // ---- warp tile geometry ----
    const int mt    = wid & 3;        // m-tile: rows [mt*16, +16)
    const int npair = wid >> 2;       // n-pair: cols [npair*16, +16)

    // ldmatrix lane addresses
    // A (x4, non-trans): lanes 0-7 m0(r0-7,k0-7), 8-15 m1(r8-15,k0-7),
    //                    16-23 m2(r0-7,k8-15), 24-31 m3(r8-15,k8-15)
    const int arow  = mt * 16 + (((lane >> 3) & 1) << 3) + (lane & 7);
    const int acol  = (lane >> 4) << 3;
    const uint32_t a_off = (uint32_t)(arow * 72 + acol) * 2u;
    // B (x4, trans): lanes 0-7 k0-7@nt0, 8-15 k8-15@nt0, 16-23 k0-7@nt1, 24-31 k8-15@nt1
    const int brow  = (((lane >> 3) & 1) << 3) + (lane & 7);
    const int bcol  = npair * 16 + ((lane >> 4) << 3);
    const uint32_t b_lane = (uint32_t)(brow * 40 + bcol) * 2u;
    const uint32_t b_hi_base = smem_base + RM_W_HI + b_lane;
    const uint32_t b_lo_base = smem_base + RM_W_LO + b_lane;

    const int b = wid * 32 + lane;    // batch row for epilogue (wid<2)
    float c_reg[8];
    #pragma unroll
    for (int i = 0; i < 8; ++i) c_reg[i] = 0.f;
    unsigned sense = 0;

    float* sG = (float*)(smc + RM_G);

    for (int t = 0; t < T_STEPS; ++t) {
        // ---- prefetch Xg tile [64 x 32] -> SMEM ----
        {
            const float* xb = g_xg + (size_t)t * B_SZ * G4;
            #pragma unroll
            for (int r = 0; r < 2; ++r) {
                int idx = tid + r * 256;                 // 0..511
                int bb = idx >> 3, q = idx & 7;          // col = q*4 (gate*8+half*4)
                const float4* p = (const float4*)(xb + (size_t)bb * G4
                                   + (size_t)(q >> 1) * H_SZ + h0 + (q & 1) * 4);
                float4 v = __ldcg(p);
                *(float4*)(smc + RM_XG + (size_t)(bb * 32 + q * 4) * 4) = v;
            }
        }

        float acc0[4] = {0.f, 0.f, 0.f, 0.f};
        float acc1[4] = {0.f, 0.f, 0.f, 0.f};

        if (t > 0) {
            const int rb = (t - 1) & 1;
            const __nv_bfloat16* Hh = g_Hh[rb];
            const __nv_bfloat16* Hl = g_Hl[rb];

            // stage-load lane mapping: idx -> (row, c8)
            const int li0 = tid, li1 = tid + 256;
            const int lr0 = li0 >> 3, lc0 = (li0 & 7) * 8;
            const int lr1 = li1 >> 3, lc1 = (li1 & 7) * 8;
            const uint32_t so0 = (uint32_t)(lr0 * 72 + lc0) * 2u;
            const uint32_t so1 = (uint32_t)(lr1 * 72 + lc1) * 2u;

            // prefetch chunk 0 into registers
            uint4 vh0 = __ldcg((const uint4*)(Hh + (size_t)lr0 * H_SZ + lc0));
            uint4 vl0 = __ldcg((const uint4*)(Hl + (size_t)lr0 * H_SZ + lc0));
            uint4 vh1 = __ldcg((const uint4*)(Hh + (size_t)lr1 * H_SZ + lc1));
            uint4 vl1 = __ldcg((const uint4*)(Hl + (size_t)lr1 * H_SZ + lc1));

            #pragma unroll 1
            for (int s = 0; s < 16; ++s) {
                char* abp = smc + RM_A + (s & 1) * 18432;
                *(uint4*)(abp + so0)        = vh0;
                *(uint4*)(abp + 9216 + so0) = vl0;
                *(uint4*)(abp + so1)        = vh1;
                *(uint4*)(abp + 9216 + so1) = vl1;
                if (s < 15) {
                    int k0 = (s + 1) * 64;
                    vh0 = __ldcg((const uint4*)(Hh + (size_t)lr0 * H_SZ + k0 + lc0));
                    vl0 = __ldcg((const uint4*)(Hl + (size_t)lr0 * H_SZ + k0 + lc0));
                    vh1 = __ldcg((const uint4*)(Hh + (size_t)lr1 * H_SZ + k0 + lc1));
                    vl1 = __ldcg((const uint4*)(Hl + (size_t)lr1 * H_SZ + k0 + lc1));
                }
                __syncthreads();

                const uint32_t a_hi = smem_base + RM_A + (s & 1) * 18432 + a_off;
                const uint32_t a_lo = a_hi + 9216;
                const uint32_t boff = (uint32_t)s * 64u * 80u;   // s*64 k-rows
                #pragma unroll
                for (int kt = 0; kt < 4; ++kt) {
                    uint32_t ah[4], al[4], bh[4], bl[4];
                    ldsm_x4 (ah, a_hi + kt * 32);
                    ldsm_x4 (al, a_lo + kt * 32);
                    ldsm_x4t(bh, b_hi_base + boff + kt * 1280);
                    ldsm_x4t(bl, b_lo_base + boff + kt * 1280);
                    mma16816(acc0, ah, bh[0], bh[1]);
                    mma16816(acc0, ah, bl[0], bl[1]);
                    mma16816(acc0, al, bh[0], bh[1]);
                    mma16816(acc1, ah, bh[2], bh[3]);
                    mma16816(acc1, ah, bl[2], bl[3]);
                    mma16816(acc1, al, bh[2], bh[3]);
                }
            }

            // store fragments to sG [64][33]
            {
                int r0  = mt * 16 + (lane >> 2);
                int col = npair * 16 + (lane & 3) * 2;
                sG[r0 * 33 + col]           = acc0[0];
                sG[r0 * 33 + col + 1]       = acc0[1];
                sG[(r0 + 8) * 33 + col]     = acc0[2];
                sG[(r0 + 8) * 33 + col + 1] = acc0[3];
                sG[r0 * 33 + col + 8]           = acc1[0];
                sG[r0 * 33 + col + 9]           = acc1[1];
                sG[(r0 + 8) * 33 + col + 8]     = acc1[2];
                sG[(r0 + 8) * 33 + col + 9]     = acc1[3];
            }
        }
        __syncthreads();   // sG + sXg visible

        // ---- epilogue: warps 0,1 (lane = batch row) ----
        if (wid < 2) {
            float g[32];
            const float* xrow = (const float*)(smc + RM_XG) + b * 32;
            if (t > 0) {
                const float* grow = sG + b * 33;
                #pragma unroll
                for (int i = 0; i < 32; ++i) g[i] = grow[i] + xrow[i];
            } else {
                #pragma unroll
                for (int i = 0; i < 32; ++i) g[i] = xrow[i];
            }

            float Hv[8];
            __nv_bfloat16 hv[8], lv[8];
            #pragma unroll
            for (int hh = 0; hh < 8; ++hh) {
                float gi = g[hh], gf = g[8 + hh], go = g[16 + hh], gc = g[24 + hh];
                float Iv = __fdividef(1.f, 1.f + __expf(-gi));
                float Fv = __fdividef(1.f, 1.f + __expf(-gf));
                float Ov = __fdividef(1.f, 1.f + __expf(-go));
                float Ct = 1.f - __fdividef(2.f, __expf(2.f * gc) + 1.f);
                float Cn = Fv * c_reg[hh] + Iv * Ct;
                c_reg[hh] = Cn;
                float th = 1.f - __fdividef(2.f, __expf(2.f * Cn) + 1.f);
                float Hn = Ov * th;
                Hv[hh] = Hn;
                __nv_bfloat16 hb = __float2bfloat16(Hn);
                hv[hh] = hb;
                lv[hh] = __float2bfloat16(Hn - __bfloat162float(hb));
            }
            float* orow = out + (size_t)t * BH + (size_t)b * H_SZ + h0;
            *(float4*)orow       = make_float4(Hv[0], Hv[1], Hv[2], Hv[3]);
            *(float4*)(orow + 4) = make_float4(Hv[4], Hv[5], Hv[6], Hv[7]);
            const int wb = t & 1;
            *(uint4*)&g_Hh[wb][(size_t)b * H_SZ + h0] = *(uint4*)hv;
            *(uint4*)&g_Hl[wb][(size_t)b * H_SZ + h0] = *(uint4*)lv;

            if (t == T_STEPS - 1) {
                size_t base = (size_t)T_STEPS * BH;
                size_t idx  = (size_t)b * H_SZ + h0;
                if ((size_t)out_size >= base + (size_t)BH) {
                    float* hp = out + base + idx;
                    *(float4*)hp       = make_float4(Hv[0], Hv[1], Hv[2], Hv[3]);
                    *(float4*)(hp + 4) = make_float4(Hv[4], Hv[5], Hv[6], Hv[7]);
                }
                if ((size_t)out_size >= base + 2 * (size_t)BH) {
                    float* cp = out + base + BH + idx;
                    *(float4*)cp       = make_float4(c_reg[0], c_reg[1], c_reg[2], c_reg[3]);
                    *(float4*)(cp + 4) = make_float4(c_reg[4], c_reg[5], c_reg[6], c_reg[7]);
                }
            }
        }

        grid_barrier(sense);   // 512 barriers/launch (even -> state restored)
    }
}

// ====================================================================
// launch
// ====================================================================
extern "C" void kernel_launch(void* const* d_in, const int* in_sizes, int n_in,
                              void* d_out, int out_size) {
    const float* X   = (const float*)d_in[0];
    const float* Wxi = (const float*)d_in[1];
    const float* Whi = (const float*)d_in[2];
    const float* bi  = (const float*)d_in[3];
    const float* Wxf = (const float*)d_in[4];
    const float* Whf = (const float*)d_in[5];
    const float* bf  = (const float*)d_in[6];
    const float* Wxo = (const float*)d_in[7];
    const float* Who = (const float*)d_in[8];
    const float* bo  = (const float*)d_in[9];
    const float* Wxc = (const float*)d_in[10];
    const float* Whc = (const float*)d_in[11];
    const float* bc  = (const float*)d_in[12];
    float* out = (float*)d_out;

    // Phase 1: input projections for all T as one big GEMM
    dim3 gA(32, 256, 1);
    xg_gemm<<<gA, 256>>>(X, Wxi, Wxf, Wxo, Wxc, bi, bf, bo, bc);

    // Phase 2: persistent mma.sync recurrence (needs >48KB dynamic SMEM)
    cudaFuncSetAttribute(lstm_rec, cudaFuncAttributeMaxDynamicSharedMemorySize,
                         RM_TOTAL);
    lstm_rec<<<NCTA, 256, RM_TOTAL>>>(Whi, Whf, Who, Whc, out, out_size);
}

// round 7
// speedup vs baseline: 3.6309x; 1.3087x over previous
#include <cuda_runtime.h>
#include <cuda_bf16.h>
#include <cstdint>
#include <math.h>

// ---------------- problem constants ----------------
#define T_STEPS 512
#define B_SZ    64
#define D_SZ    512
#define H_SZ    1024
#define G4      4096          // 4*H
#define BH      (B_SZ*H_SZ)   // 65536
#define NCTA    128

// ---------------- global scratch / sync state ----------------
__device__ float g_xg[(size_t)T_STEPS * B_SZ * G4];   // 512 MB, Xg = X@Wx + b
__device__ __nv_bfloat16 g_Hh[2][BH];                 // H split-bf16 hi, ping-pong
__device__ __nv_bfloat16 g_Hl[2][BH];                 // H split-bf16 lo
__device__ __nv_bfloat16 g_Xh[(size_t)T_STEPS * B_SZ * D_SZ];   // X split hi
__device__ __nv_bfloat16 g_Xl[(size_t)T_STEPS * B_SZ * D_SZ];   // X split lo
__device__ __nv_bfloat16 g_Wxh[(size_t)D_SZ * G4];    // Wx concat split hi
__device__ __nv_bfloat16 g_Wxl[(size_t)D_SZ * G4];    // Wx concat split lo
__device__ float g_bcat[G4];                          // bias concat
__device__ int      g_ready[NCTA];                    // per-CTA step counter (x2)
__device__ unsigned g_arrive = 0;
__device__ unsigned g_gen    = 0;

// ---------------- helpers ----------------
__device__ __forceinline__ uint32_t smem_u32(const void* p) {
    uint32_t a;
    asm("{ .reg .u64 t; cvta.to.shared.u64 t, %1; cvt.u32.u64 %0, t; }" : "=r"(a) : "l"(p));
    return a;
}
__device__ __forceinline__ void ldsm_x4(uint32_t* r, uint32_t addr) {
    asm volatile("ldmatrix.sync.aligned.m8n8.x4.shared.b16 {%0,%1,%2,%3}, [%4];"
                 : "=r"(r[0]), "=r"(r[1]), "=r"(r[2]), "=r"(r[3]) : "r"(addr));
}
__device__ __forceinline__ void ldsm_x4t(uint32_t* r, uint32_t addr) {
    asm volatile("ldmatrix.sync.aligned.m8n8.x4.trans.shared.b16 {%0,%1,%2,%3}, [%4];"
                 : "=r"(r[0]), "=r"(r[1]), "=r"(r[2]), "=r"(r[3]) : "r"(addr));
}
__device__ __forceinline__ void mma16816(float* c, const uint32_t* a, uint32_t b0, uint32_t b1) {
    asm volatile(
        "mma.sync.aligned.m16n8k16.row.col.f32.bf16.bf16.f32 "
        "{%0,%1,%2,%3}, {%4,%5,%6,%7}, {%8,%9}, {%0,%1,%2,%3};"
        : "+f"(c[0]), "+f"(c[1]), "+f"(c[2]), "+f"(c[3])
        : "r"(a[0]), "r"(a[1]), "r"(a[2]), "r"(a[3]), "r"(b0), "r"(b1));
}
__device__ __forceinline__ void cp16(uint32_t saddr, const void* g) {
    asm volatile("cp.async.cg.shared.global [%0], [%1], 16;" :: "r"(saddr), "l"(g));
}
#define CP_COMMIT() asm volatile("cp.async.commit_group;" ::: "memory")
#define CP_WAIT(N)  asm volatile("cp.async.wait_group %0;" :: "n"(N) : "memory")

__device__ __forceinline__ void wait_ready(int idx, int target) {
    int v;
    do {
        asm volatile("ld.acquire.gpu.s32 %0, [%1];" : "=r"(v) : "l"(g_ready + idx) : "memory");
        if (v < target) __nanosleep(32);
    } while (v < target);
}

// self-resetting generation barrier (replay-safe: g_arrive returns to 0,
// g_gen monotone; identical work every launch)
__device__ __forceinline__ void init_barrier() {
    __syncthreads();
    if (threadIdx.x == 0) {
        __threadfence();
        unsigned gen;
        asm volatile("ld.acquire.gpu.u32 %0, [%1];" : "=r"(gen) : "l"(&g_gen) : "memory");
        unsigned old = atomicAdd(&g_arrive, 1u);
        if (old == NCTA - 1) {
            atomicExch(&g_arrive, 0u);
            __threadfence();
            atomicAdd(&g_gen, 1u);
        } else {
            unsigned cur;
            do {
                __nanosleep(64);
                asm volatile("ld.acquire.gpu.u32 %0, [%1];" : "=r"(cur) : "l"(&g_gen) : "memory");
            } while (cur == gen);
        }
        __threadfence();
    }
    __syncthreads();
}

__device__ __forceinline__ void split2u(float v, unsigned& h, unsigned& l) {
    __nv_bfloat16 hb = __float2bfloat16(v);
    float r = v - __bfloat162float(hb);
    __nv_bfloat16 lb = __float2bfloat16(r);
    h = (unsigned)*reinterpret_cast<unsigned short*>(&hb);
    l = (unsigned)*reinterpret_cast<unsigned short*>(&lb);
}

// ====================================================================
// Kernel 0: split X and Wx (concat) into bf16 hi/lo; build bias concat.
// ====================================================================
#define NX4 ((size_t)T_STEPS * B_SZ * D_SZ / 4)      // 4,194,304
#define NW4 ((size_t)D_SZ * G4 / 4)                  // 524,288

__global__ void __launch_bounds__(256) conv_prep(
    const float* __restrict__ X,
    const float* __restrict__ Wx0, const float* __restrict__ Wx1,
    const float* __restrict__ Wx2, const float* __restrict__ Wx3,
    const float* __restrict__ b0p, const float* __restrict__ b1p,
    const float* __restrict__ b2p, const float* __restrict__ b3p)
{
    size_t i = (size_t)blockIdx.x * 256 + threadIdx.x;
    if (i < NX4) {
        float4 v = ((const float4*)X)[i];
        unsigned h0, h1, h2, h3, l0, l1, l2, l3;
        split2u(v.x, h0, l0); split2u(v.y, h1, l1);
        split2u(v.z, h2, l2); split2u(v.w, h3, l3);
        *(uint2*)&g_Xh[i * 4] = make_uint2(h0 | (h1 << 16), h2 | (h3 << 16));
        *(uint2*)&g_Xl[i * 4] = make_uint2(l0 | (l1 << 16), l2 | (l3 << 16));
    } else if (i < NX4 + NW4) {
        size_t d = i - NX4;
        int k  = (int)(d >> 10);            // 1024 float4 per 4096-col row
        int c4 = (int)(d & 1023);
        int col  = c4 * 4;
        int gate = col >> 10;
        int n    = col & 1023;
        const float* W = (gate == 0) ? Wx0 : (gate == 1) ? Wx1 : (gate == 2) ? Wx2 : Wx3;
        float4 v = *(const float4*)&W[(size_t)k * 1024 + n];
        unsigned h0, h1, h2, h3, l0, l1, l2, l3;
        split2u(v.x, h0, l0); split2u(v.y, h1, l1);
        split2u(v.z, h2, l2); split2u(v.w, h3, l3);
        *(uint2*)&g_Wxh[d * 4] = make_uint2(h0 | (h1 << 16), h2 | (h3 << 16));
        *(uint2*)&g_Wxl[d * 4] = make_uint2(l0 | (l1 << 16), l2 | (l3 << 16));
    }
    if (i < G4 / 4) {
        int col = (int)i * 4;
        int gate = col >> 10, n = col & 1023;
        const float* bg = (gate == 0) ? b0p : (gate == 1) ? b1p : (gate == 2) ? b2p : b3p;
        ((float4*)g_bcat)[i] = *(const float4*)&bg[n];
    }
}

// ====================================================================
// Kernel 1: Xg = X @ Wxcat + bcat via split-bf16 3-pass mma.sync.
// CTA tile 128(m) x 128(n), K=512 in 8 chunks of 64, cp.async double buf.
// 8 warps: warp tile 32(m) x 64(n).
// ====================================================================
#define XA_HI(buf) ((buf)*36864)                   // [128][72] bf16
#define XA_LO(buf) ((buf)*36864 + 18432)
#define XB_HI(buf) (73728 + (buf)*34816)           // [64][136] bf16
#define XB_LO(buf) (73728 + (buf)*34816 + 17408)
#define XG_SMEM    143360

__global__ void __launch_bounds__(256, 1) xg_mma()
{
    extern __shared__ char smc[];
    const uint32_t smem_base = smem_u32(smc);
    const int tid  = threadIdx.x;
    const int wid  = tid >> 5;
    const int lane = tid & 31;
    const int m0   = blockIdx.y * 128;
    const int nb   = blockIdx.x * 128;
    const int mw   = (wid & 3) * 32;
    const int nw   = (wid >> 2) * 64;

    // ldmatrix lane addressing (same proven patterns as lstm_rec)
    const int arow = ((lane >> 3) & 1) * 8 + (lane & 7);
    const int acol = (lane >> 4) * 8;
    const int brow = ((lane >> 3) & 1) * 8 + (lane & 7);
    const int bcol = (lane >> 4) * 8;

    float acc[2][8][4];
    #pragma unroll
    for (int m = 0; m < 2; ++m)
        #pragma unroll
        for (int n = 0; n < 8; ++n)
            #pragma unroll
            for (int q = 0; q < 4; ++q) acc[m][n][q] = 0.f;

    auto issue_chunk = [&](int s, int buf) {
        // A: 128 rows x 64 k  (1024 x 16B)
        #pragma unroll
        for (int i = 0; i < 4; ++i) {
            int idx = tid + i * 256;
            int row = idx >> 3, c8 = (idx & 7) * 8;
            uint32_t sa = smem_base + XA_HI(buf) + (uint32_t)(row * 72 + c8) * 2u;
            size_t go = (size_t)(m0 + row) * D_SZ + s * 64 + c8;
            cp16(sa,          g_Xh + go);
            cp16(sa + 18432u, g_Xl + go);
        }
        // B: 64 k x 128 n  (1024 x 16B)
        #pragma unroll
        for (int i = 0; i < 4; ++i) {
            int idx = tid + i * 256;
            int r = idx >> 4, c8 = (idx & 15) * 8;
            uint32_t sb = smem_base + XB_HI(buf) + (uint32_t)(r * 136 + c8) * 2u;
            size_t go = (size_t)(s * 64 + r) * G4 + nb + c8;
            cp16(sb,          g_Wxh + go);
            cp16(sb + 17408u, g_Wxl + go);
        }
        CP_COMMIT();
    };

    issue_chunk(0, 0);
    #pragma unroll 1
    for (int s = 0; s < 8; ++s) {
        if (s < 7) { issue_chunk(s + 1, (s + 1) & 1); CP_WAIT(1); }
        else       { CP_WAIT(0); }
        __syncthreads();

        const int buf = s & 1;
        const uint32_t Ah = smem_base + XA_HI(buf);
        const uint32_t Bh = smem_base + XB_HI(buf);
        #pragma unroll
        for (int kt = 0; kt < 4; ++kt) {
            uint32_t ah[2][4], al[2][4];
            #pragma unroll
            for (int m = 0; m < 2; ++m) {
                uint32_t ar = Ah + (uint32_t)((mw + m * 16 + arow) * 72 + kt * 16 + acol) * 2u;
                ldsm_x4(ah[m], ar);
                ldsm_x4(al[m], ar + 18432u);
            }
            uint32_t bh[4][4], bl[4][4];
            #pragma unroll
            for (int np = 0; np < 4; ++np) {
                uint32_t br = Bh + (uint32_t)((kt * 16 + brow) * 136 + nw + np * 16 + bcol) * 2u;
                ldsm_x4t(bh[np], br);
                ldsm_x4t(bl[np], br + 17408u);
            }
            #pragma unroll
            for (int m = 0; m < 2; ++m)
                #pragma unroll
                for (int np = 0; np < 4; ++np) {
                    mma16816(acc[m][2*np],   ah[m], bh[np][0], bh[np][1]);
                    mma16816(acc[m][2*np],   ah[m], bl[np][0], bl[np][1]);
                    mma16816(acc[m][2*np],   al[m], bh[np][0], bh[np][1]);
                    mma16816(acc[m][2*np+1], ah[m], bh[np][2], bh[np][3]);
                    mma16816(acc[m][2*np+1], ah[m], bl[np][2], bl[np][3]);
                    mma16816(acc[m][2*np+1], al[m], bh[np][2], bh[np][3]);
                }
        }
        __syncthreads();
    }

    // epilogue: add bias, store fp32 Xg
    const int r0    = m0 + mw + (lane >> 2);
    const int cbase = nb + nw + (lane & 3) * 2;
    #pragma unroll
    for (int m = 0; m < 2; ++m) {
        #pragma unroll
        for (int nt = 0; nt < 8; ++nt) {
            int col = cbase + nt * 8;
            float b0 = g_bcat[col], b1 = g_bcat[col + 1];
            int rr = r0 + m * 16;
            float* p0 = g_xg + (size_t)rr * G4 + col;
            float* p1 = g_xg + (size_t)(rr + 8) * G4 + col;
            *(float2*)p0 = make_float2(acc[m][nt][0] + b0, acc[m][nt][1] + b1);
            *(float2*)p1 = make_float2(acc[m][nt][2] + b0, acc[m][nt][3] + b1);
        }
    }
}

// ====================================================================
// Kernel 2: persistent mma.sync recurrence, flag-based wavefront sync.
// 128 CTAs x 256 threads, 1/SM. CTA j owns h-slice [j*8,j*8+8) for 4 gates
// -> 32 gate columns. Per step: G[64,32] = H@Whslice, 3-pass split-bf16.
// Chunk s of K needs H cols [64s,64s+64) = slices of CTAs 8s..8s+7 only:
// consumers poll per-CTA monotone ready counters (2 per step), with the
// flag load pre-issued 2 chunks ahead so the check is off critical path.
// Safety with 2 H buffers: writer of H[t+1] already waited ready>=2(t+1)
// from ALL CTAs (chunks cover all 128) => everyone finished reading H[t-1].
// ====================================================================

#define RM_W_HI 0                      // 1024 x 40 bf16 = 81920
#define RM_W_LO 81920
#define RM_A    163840                 // 2 bufs x {hi,lo} x 64x72 bf16
#define RM_XG   200704                 // 64x32 f32
#define RM_G    208896                 // 64x33 f32
#define RM_TOTAL 217344

__global__ void __launch_bounds__(256, 1) lstm_rec(
    const float* __restrict__ Wh0, const float* __restrict__ Wh1,
    const float* __restrict__ Wh2, const float* __restrict__ Wh3,
    float* __restrict__ out, int out_size)
{
    extern __shared__ char smc[];
    const uint32_t smem_base = smem_u32(smc);
    const int tid  = threadIdx.x;
    const int wid  = tid >> 5;
    const int lane = tid & 31;
    const int h0   = blockIdx.x * 8;

    if (tid == 0) g_ready[blockIdx.x] = 0;

    // ---- fill resident Wh slice: [k][n=gate*8+hh], stride 40, hi+lo ----
    {
        __nv_bfloat16* wh = (__nv_bfloat16*)(smc + RM_W_HI);
        __nv_bfloat16* wl = (__nv_bfloat16*)(smc + RM_W_LO);
        for (int i = tid; i < 32 * 1024; i += 256) {
            int k = i >> 5, n = i & 31;
            int gate = n >> 3;
            const float* W = (gate == 0) ? Wh0 : (gate == 1) ? Wh1
                             : (gate == 2) ? Wh2 : Wh3;
            float w = W[(size_t)k * H_SZ + h0 + (n & 7)];
            __nv_bfloat16 hi = __float2bfloat16(w);
            __nv_bfloat16 lo = __float2bfloat16(w - __bfloat162float(hi));
            wh[k * 40 + n] = hi;
            wl[k * 40 + n] = lo;
        }
    }
    init_barrier();   // flags reset globally visible; also syncs Wh fill

    // ---- warp tile geometry ----
    const int mt    = wid & 3;
    const int npair = wid >> 2;
    const int arow  = mt * 16 + (((lane >> 3) & 1) << 3) + (lane & 7);
    const int acol  = (lane >> 4) << 3;
    const uint32_t a_off = (uint32_t)(arow * 72 + acol) * 2u;
    const int brow  = (((lane >> 3) & 1) << 3) + (lane & 7);
    const int bcol  = npair * 16 + ((lane >> 4) << 3);
    const uint32_t b_lane = (uint32_t)(brow * 40 + bcol) * 2u;
    const uint32_t b_hi_base = smem_base + RM_W_HI + b_lane;
    const uint32_t b_lo_base = smem_base + RM_W_LO + b_lane;

    const int b  = wid * 32 + lane;   // batch row for epilogue (wid<2)
    const int fc = tid & 7;           // producer sub-index within a chunk
    float c_reg[8];
    #pragma unroll
    for (int i = 0; i < 8; ++i) c_reg[i] = 0.f;

    float* sG = (float*)(smc + RM_G);

    for (int t = 0; t < T_STEPS; ++t) {
        // ---- prefetch Xg tile [64 x 32] -> SMEM ----
        {
            const float* xb = g_xg + (size_t)t * B_SZ * G4;
            #pragma unroll
            for (int r = 0; r < 2; ++r) {
                int idx = tid + r * 256;
                int bb = idx >> 3, q = idx & 7;
                const float4* p = (const float4*)(xb + (size_t)bb * G4
                                   + (size_t)(q >> 1) * H_SZ + h0 + (q & 1) * 4);
                float4 v = __ldcg(p);
                *(float4*)(smc + RM_XG + (size_t)(bb * 32 + q * 4) * 4) = v;
            }
        }

        float acc0[4] = {0.f, 0.f, 0.f, 0.f};
        float acc1[4] = {0.f, 0.f, 0.f, 0.f};

        if (t > 0) {
            const int rb = (t - 1) & 1;
            const __nv_bfloat16* Hh = g_Hh[rb];
            const __nv_bfloat16* Hl = g_Hl[rb];
            const int need = 2 * t;

            const int li1 = tid + 256;
            const int lr0 = tid >> 3, lc0 = (tid & 7) * 8;
            const int lr1 = li1 >> 3, lc1 = (li1 & 7) * 8;
            const uint32_t so0 = (uint32_t)(lr0 * 72 + lc0) * 2u;
            const uint32_t so1 = (uint32_t)(lr1 * 72 + lc1) * 2u;

            // chunk 0: wait producers, prefetch into registers
            {
                int fv = __ldcg(&g_ready[fc]);
                if (fv < need) wait_ready(fc, need);
            }
            uint4 vh0 = __ldcg((const uint4*)(Hh + (size_t)lr0 * H_SZ + lc0));
            uint4 vl0 = __ldcg((const uint4*)(Hl + (size_t)lr0 * H_SZ + lc0));
            uint4 vh1 = __ldcg((const uint4*)(Hh + (size_t)lr1 * H_SZ + lc1));
            uint4 vl1 = __ldcg((const uint4*)(Hl + (size_t)lr1 * H_SZ + lc1));
            int fv2 = __ldcg(&g_ready[8 + fc]);   // chunk 1 flag, issued early

            #pragma unroll 1
            for (int s = 0; s < 16; ++s) {
                char* abp = smc + RM_A + (s & 1) * 18432;
                *(uint4*)(abp + so0)        = vh0;
                *(uint4*)(abp + 9216 + so0) = vl0;
                *(uint4*)(abp + so1)        = vh1;
                *(uint4*)(abp + 9216 + so1) = vl1;
                if (s < 15) {
                    if (fv2 < need) wait_ready((s + 1) * 8 + fc, need);
                    int k0 = (s + 1) * 64;
                    vh0 = __ldcg((const uint4*)(Hh + (size_t)lr0 * H_SZ + k0 + lc0));
                    vl0 = __ldcg((const uint4*)(Hl + (size_t)lr0 * H_SZ + k0 + lc0));
                    vh1 = __ldcg((const uint4*)(Hh + (size_t)lr1 * H_SZ + k0 + lc1));
                    vl1 = __ldcg((const uint4*)(Hl + (size_t)lr1 * H_SZ + k0 + lc1));
                    if (s < 14) fv2 = __ldcg(&g_ready[(s + 2) * 8 + fc]);
                }
                __syncthreads();

                const uint32_t a_hi = smem_base + RM_A + (s & 1) * 18432 + a_off;
                const uint32_t a_lo = a_hi + 9216;
                const uint32_t boff = (uint32_t)s * 64u * 80u;
                #pragma unroll
                for (int kt = 0; kt < 4; ++kt) {
                    uint32_t ah[4], al[4], bh[4], bl[4];
                    ldsm_x4 (ah, a_hi + kt * 32);
                    ldsm_x4 (al, a_lo + kt * 32);
                    ldsm_x4t(bh, b_hi_base + boff + kt * 1280);
                    ldsm_x4t(bl, b_lo_base + boff + kt * 1280);
                    mma16816(acc0, ah, bh[0], bh[1]);
                    mma16816(acc0, ah, bl[0], bl[1]);
                    mma16816(acc0, al, bh[0], bh[1]);
                    mma16816(acc1, ah, bh[2], bh[3]);
                    mma16816(acc1, ah, bl[2], bl[3]);
                    mma16816(acc1, al, bh[2], bh[3]);
                }
            }

            // store fragments to sG [64][33]
            {
                int r0  = mt * 16 + (lane >> 2);
                int col = npair * 16 + (lane & 3) * 2;
                sG[r0 * 33 + col]           = acc0[0];
                sG[r0 * 33 + col + 1]       = acc0[1];
                sG[(r0 + 8) * 33 + col]     = acc0[2];
                sG[(r0 + 8) * 33 + col + 1] = acc0[3];
                sG[r0 * 33 + col + 8]           = acc1[0];
                sG[r0 * 33 + col + 9]           = acc1[1];
                sG[(r0 + 8) * 33 + col + 8]     = acc1[2];
                sG[(r0 + 8) * 33 + col + 9]     = acc1[3];
            }
        }
        __syncthreads();   // sG + sXg visible to epilogue

        // ---- epilogue: warps 0,1 (lane = batch row) ----
        if (wid < 2) {
            float g[32];
            const float* xrow = (const float*)(smc + RM_XG) + b * 32;
            if (t > 0) {
                const float* grow = sG + b * 33;
                #pragma unroll
                for (int i = 0; i < 32; ++i) g[i] = grow[i] + xrow[i];
            } else {
                #pragma unroll
                for (int i = 0; i < 32; ++i) g[i] = xrow[i];
            }

            float Hv[8];
            __nv_bfloat16 hv[8], lv[8];
            #pragma unroll
            for (int hh = 0; hh < 8; ++hh) {
                float gi = g[hh], gf = g[8 + hh], go = g[16 + hh], gc = g[24 + hh];
                float Iv = __fdividef(1.f, 1.f + __expf(-gi));
                float Fv = __fdividef(1.f, 1.f + __expf(-gf));
                float Ov = __fdividef(1.f, 1.f + __expf(-go));
                float Ct = 1.f - __fdividef(2.f, __expf(2.f * gc) + 1.f);
                float Cn = Fv * c_reg[hh] + Iv * Ct;
                c_reg[hh] = Cn;
                float th = 1.f - __fdividef(2.f, __expf(2.f * Cn) + 1.f);
                float Hn = Ov * th;
                Hv[hh] = Hn;
                __nv_bfloat16 hb = __float2bfloat16(Hn);
                hv[hh] = hb;
                lv[hh] = __float2bfloat16(Hn - __bfloat162float(hb));
            }
            float* orow = out + (size_t)t * BH + (size_t)b * H_SZ + h0;
            *(float4*)orow       = make_float4(Hv[0], Hv[1], Hv[2], Hv[3]);
            *(float4*)(orow + 4) = make_float4(Hv[4], Hv[5], Hv[6], Hv[7]);
            const int wb = t & 1;
            *(uint4*)&g_Hh[wb][(size_t)b * H_SZ + h0] = *(uint4*)hv;
            *(uint4*)&g_Hl[wb][(size_t)b * H_SZ + h0] = *(uint4*)lv;

            if (t == T_STEPS - 1) {
                size_t base = (size_t)T_STEPS * BH;
                size_t idx  = (size_t)b * H_SZ + h0;
                if ((size_t)out_size >= base + (size_t)BH) {
                    float* hp = out + base + idx;
                    *(float4*)hp       = make_float4(Hv[0], Hv[1], Hv[2], Hv[3]);
                    *(float4*)(hp + 4) = make_float4(Hv[4], Hv[5], Hv[6], Hv[7]);
                }
                if ((size_t)out_size >= base + 2 * (size_t)BH) {
                    float* cp = out + base + BH + idx;
                    *(float4*)cp       = make_float4(c_reg[0], c_reg[1], c_reg[2], c_reg[3]);
                    *(float4*)(cp + 4) = make_float4(c_reg[4], c_reg[5], c_reg[6], c_reg[7]);
                }
            }

            __threadfence();   // release H-slice writes
            if (lane == 0) atomicAdd(&g_ready[blockIdx.x], 1);
        }
        __syncthreads();   // protect sXg/sG for next step
    }
}

// ====================================================================
// launch
// ====================================================================
extern "C" void kernel_launch(void* const* d_in, const int* in_sizes, int n_in,
                              void* d_out, int out_size) {
    const float* X   = (const float*)d_in[0];
    const float* Wxi = (const float*)d_in[1];
    const float* Whi = (const float*)d_in[2];
    const float* bi  = (const float*)d_in[3];
    const float* Wxf = (const float*)d_in[4];
    const float* Whf = (const float*)d_in[5];
    const float* bf  = (const float*)d_in[6];
    const float* Wxo = (const float*)d_in[7];
    const float* Who = (const float*)d_in[8];
    const float* bo  = (const float*)d_in[9];
    const float* Wxc = (const float*)d_in[10];
    const float* Whc = (const float*)d_in[11];
    const float* bc  = (const float*)d_in[12];
    float* out = (float*)d_out;

    // Phase 0: split X / Wx into bf16 hi/lo, build bias concat
    int cblocks = (int)((NX4 + NW4) / 256);
    conv_prep<<<cblocks, 256>>>(X, Wxi, Wxf, Wxo, Wxc, bi, bf, bo, bc);

    // Phase 1: Xg = X @ Wxcat + b via tensor cores
    cudaFuncSetAttribute(xg_mma, cudaFuncAttributeMaxDynamicSharedMemorySize,
                         XG_SMEM);
    xg_mma<<<dim3(32, 256), 256, XG_SMEM>>>();

    // Phase 2: persistent recurrence with wavefront flags
    cudaFuncSetAttribute(lstm_rec, cudaFuncAttributeMaxDynamicSharedMemorySize,
                         RM_TOTAL);
    lstm_rec<<<NCTA, 256, RM_TOTAL>>>(Whi, Whf, Who, Whc, out, out_size);
}